// round 2
// baseline (speedup 1.0000x reference)
#include <cuda_runtime.h>

#define NN 100000
#define NE 1600000
#define ET (NE + NN)

// -------- scratch (device globals: no allocations allowed) --------
__device__ int   g_src[ET];
__device__ int   g_dst[ET];
__device__ float g_h1[NN * 128];   // layer1 features [N,8,16]
__device__ float g_as1[NN * 8];    // a_src layer1
__device__ float g_ad1[NN * 8];    // a_dst layer1
__device__ float g_dn1[NN * 8];    // softmax denom layer1
__device__ float g_o1[NN * 128];   // layer1 aggregate -> elu'd in place (h2)
__device__ float g_z[NN * 40];     // layer2 features
__device__ float g_as2[NN];
__device__ float g_ad2[NN];
__device__ float g_dn2[NN];

__device__ __forceinline__ void red_add_v4(float* p, float a, float b, float c, float d) {
    asm volatile("red.global.add.v4.f32 [%0], {%1,%2,%3,%4};"
                 :: "l"(p), "f"(a), "f"(b), "f"(c), "f"(d) : "memory");
}

__device__ __forceinline__ float lrelu(float v) { return v > 0.f ? v : 0.2f * v; }

// ==================== repack edges (dtype-robust) + append self loops ====================
// If the harness delivered int64 (little-endian), the odd 32-bit words of the
// first entries are zero high-words. With int32 data those words are random
// indices in [0,100000) — 16 consecutive zeros is impossible in practice.
__global__ void repack(const int* __restrict__ e32) {
    __shared__ int is64;
    if (threadIdx.x == 0) {
        int z = 0;
#pragma unroll
        for (int j = 1; j <= 16; j++) z |= e32[2 * j + 1];
        is64 = (z == 0) ? 1 : 0;
    }
    __syncthreads();
    int i = blockIdx.x * blockDim.x + threadIdx.x;
    if (i >= ET) return;
    if (i < NE) {
        if (is64) { g_src[i] = e32[2 * i];  g_dst[i] = e32[2 * (NE + i)]; }
        else      { g_src[i] = e32[i];      g_dst[i] = e32[NE + i]; }
    } else {
        g_src[i] = i - NE;
        g_dst[i] = i - NE;
    }
}

// ==================== GEMM1: h1 = x @ W1, + attention dots ====================
// block: 256 threads, 32 rows. Ws in smem (64KB), xs 32x129 padded.
__global__ void gemm1_kernel(const float* __restrict__ x, const float* __restrict__ W,
                             const float* __restrict__ atts, const float* __restrict__ attd) {
    extern __shared__ float sm[];
    float* Ws = sm;           // 128*128
    float* xs = sm + 16384;   // 32*129
    int t = threadIdx.x;
    int ct = t & 31, rt = t >> 5;
    int row0 = blockIdx.x * 32;

    for (int i = t; i < 16384; i += 256) Ws[i] = W[i];
    for (int i = t; i < 4096; i += 256) {
        int r = i >> 7, k = i & 127;
        xs[r * 129 + k] = x[(row0 + r) * 128 + k];
    }
    __syncthreads();

    float acc[4][4] = {};
#pragma unroll 4
    for (int k = 0; k < 128; k++) {
        float4 w = *(const float4*)&Ws[k * 128 + 4 * ct];
#pragma unroll
        for (int i = 0; i < 4; i++) {
            float xv = xs[(rt * 4 + i) * 129 + k];
            acc[i][0] += xv * w.x; acc[i][1] += xv * w.y;
            acc[i][2] += xv * w.z; acc[i][3] += xv * w.w;
        }
    }

    float4 avs = *(const float4*)&atts[4 * ct];
    float4 avd = *(const float4*)&attd[4 * ct];
#pragma unroll
    for (int i = 0; i < 4; i++) {
        int row = row0 + rt * 4 + i;
        *(float4*)&g_h1[row * 128 + 4 * ct] =
            make_float4(acc[i][0], acc[i][1], acc[i][2], acc[i][3]);
        float ps = acc[i][0] * avs.x + acc[i][1] * avs.y + acc[i][2] * avs.z + acc[i][3] * avs.w;
        float pd = acc[i][0] * avd.x + acc[i][1] * avd.y + acc[i][2] * avd.z + acc[i][3] * avd.w;
        ps += __shfl_xor_sync(0xffffffffu, ps, 1);
        ps += __shfl_xor_sync(0xffffffffu, ps, 2);
        pd += __shfl_xor_sync(0xffffffffu, pd, 1);
        pd += __shfl_xor_sync(0xffffffffu, pd, 2);
        if ((ct & 3) == 0) {
            g_as1[row * 8 + (ct >> 2)] = ps;
            g_ad1[row * 8 + (ct >> 2)] = pd;
        }
    }
}

// ==================== layer1 edge pass 1: softmax denominators ====================
__global__ void l1_denom() {
    int i = blockIdx.x * blockDim.x + threadIdx.x;
    if (i >= ET) return;
    int s = g_src[i], d = g_dst[i];
    float4 s0 = *(const float4*)&g_as1[s * 8];
    float4 s1 = *(const float4*)&g_as1[s * 8 + 4];
    float4 d0 = *(const float4*)&g_ad1[d * 8];
    float4 d1 = *(const float4*)&g_ad1[d * 8 + 4];
    red_add_v4(&g_dn1[d * 8],
               __expf(lrelu(s0.x + d0.x)), __expf(lrelu(s0.y + d0.y)),
               __expf(lrelu(s0.z + d0.z)), __expf(lrelu(s0.w + d0.w)));
    red_add_v4(&g_dn1[d * 8 + 4],
               __expf(lrelu(s1.x + d1.x)), __expf(lrelu(s1.y + d1.y)),
               __expf(lrelu(s1.z + d1.z)), __expf(lrelu(s1.w + d1.w)));
}

// ==================== layer1 edge pass 2: weighted aggregation ====================
// warp per edge: lane covers cols lane*4..lane*4+3 (head = lane/4).
__global__ void l1_agg() {
    int w = (blockIdx.x * blockDim.x + threadIdx.x) >> 5;
    int lane = threadIdx.x & 31;
    if (w >= ET) return;
    int s = g_src[w], d = g_dst[w];
    float alpha = 0.f;
    if (lane < 8) {
        float e = lrelu(g_as1[s * 8 + lane] + g_ad1[d * 8 + lane]);
        alpha = __expf(e) / (g_dn1[d * 8 + lane] + 1e-16f);
    }
    alpha = __shfl_sync(0xffffffffu, alpha, lane >> 2);
    float4 v = *(const float4*)&g_h1[s * 128 + lane * 4];
    red_add_v4(&g_o1[d * 128 + lane * 4],
               alpha * v.x, alpha * v.y, alpha * v.z, alpha * v.w);
}

// ==================== bias + ELU (in place on g_o1) ====================
__global__ void bias_elu(const float* __restrict__ b1) {
    int i = blockIdx.x * blockDim.x + threadIdx.x;
    if (i >= NN * 128) return;
    float v = g_o1[i] + b1[i & 127];
    g_o1[i] = v > 0.f ? v : expm1f(v);
}

// ==================== GEMM2: z = h2 @ W2 (128 -> 40) ====================
__global__ void gemm2_kernel(const float* __restrict__ W) {
    extern __shared__ float sm[];
    float* Ws = sm;           // 128*40 = 5120
    float* xs = sm + 5120;    // 64*129
    int t = threadIdx.x;
    int ct = t % 10, rt = t / 10;
    int row0 = blockIdx.x * 64;

    for (int i = t; i < 5120; i += 160) Ws[i] = W[i];
    for (int i = t; i < 8192; i += 160) {
        int r = i >> 7, k = i & 127;
        int row = row0 + r;
        xs[r * 129 + k] = (row < NN) ? g_o1[row * 128 + k] : 0.f;
    }
    __syncthreads();

    float acc[4][4] = {};
#pragma unroll 2
    for (int k = 0; k < 128; k++) {
        float4 w = *(const float4*)&Ws[k * 40 + 4 * ct];
#pragma unroll
        for (int i = 0; i < 4; i++) {
            float xv = xs[(rt * 4 + i) * 129 + k];
            acc[i][0] += xv * w.x; acc[i][1] += xv * w.y;
            acc[i][2] += xv * w.z; acc[i][3] += xv * w.w;
        }
    }
#pragma unroll
    for (int i = 0; i < 4; i++) {
        int row = row0 + rt * 4 + i;
        if (row < NN)
            *(float4*)&g_z[row * 40 + 4 * ct] =
                make_float4(acc[i][0], acc[i][1], acc[i][2], acc[i][3]);
    }
}

// ==================== layer2 attention dots (warp per row) ====================
__global__ void a2_kernel(const float* __restrict__ atts, const float* __restrict__ attd) {
    int w = (blockIdx.x * blockDim.x + threadIdx.x) >> 5;
    int lane = threadIdx.x & 31;
    if (w >= NN) return;
    float ps = 0.f, pd = 0.f;
    for (int c = lane; c < 40; c += 32) {
        float v = g_z[w * 40 + c];
        ps += v * atts[c];
        pd += v * attd[c];
    }
    for (int o = 16; o; o >>= 1) {
        ps += __shfl_xor_sync(0xffffffffu, ps, o);
        pd += __shfl_xor_sync(0xffffffffu, pd, o);
    }
    if (lane == 0) { g_as2[w] = ps; g_ad2[w] = pd; }
}

// ==================== layer2 edge pass 1 ====================
__global__ void l2_denom() {
    int i = blockIdx.x * blockDim.x + threadIdx.x;
    if (i >= ET) return;
    int s = g_src[i], d = g_dst[i];
    float e = lrelu(g_as2[s] + g_ad2[d]);
    atomicAdd(&g_dn2[d], __expf(e));
}

// ==================== layer2 edge pass 2 (warp per edge, 10 active lanes) ====================
__global__ void l2_agg(float* __restrict__ out) {
    int w = (blockIdx.x * blockDim.x + threadIdx.x) >> 5;
    int lane = threadIdx.x & 31;
    if (w >= ET) return;
    int s = g_src[w], d = g_dst[w];
    if (lane < 10) {
        float e = lrelu(g_as2[s] + g_ad2[d]);
        float alpha = __expf(e) / (g_dn2[d] + 1e-16f);
        float4 v = *(const float4*)&g_z[s * 40 + lane * 4];
        red_add_v4(&out[d * 40 + lane * 4],
                   alpha * v.x, alpha * v.y, alpha * v.z, alpha * v.w);
    }
}

// ==================== bias2 + log_softmax, in place on out ====================
__global__ void lsm_kernel(float* __restrict__ out, const float* __restrict__ b2) {
    int w = (blockIdx.x * blockDim.x + threadIdx.x) >> 5;
    int lane = threadIdx.x & 31;
    if (w >= NN) return;
    float v1 = out[w * 40 + lane] + b2[lane];
    float v2 = (lane < 8) ? out[w * 40 + 32 + lane] + b2[32 + lane] : -1e30f;
    float m = fmaxf(v1, v2);
    for (int o = 16; o; o >>= 1) m = fmaxf(m, __shfl_xor_sync(0xffffffffu, m, o));
    float s = expf(v1 - m) + ((lane < 8) ? expf(v2 - m) : 0.f);
    for (int o = 16; o; o >>= 1) s += __shfl_xor_sync(0xffffffffu, s, o);
    float ls = m + logf(s);
    out[w * 40 + lane] = v1 - ls;
    if (lane < 8) out[w * 40 + 32 + lane] = v2 - ls;
}

// ==================== launch ====================
extern "C" void kernel_launch(void* const* d_in, const int* in_sizes, int n_in,
                              void* d_out, int out_size) {
    const float* x   = (const float*)d_in[0];
    const int*   ei  = (const int*)d_in[1];   // dtype auto-detected in repack
    const float* W1  = (const float*)d_in[2];
    const float* as1 = (const float*)d_in[3];
    const float* ad1 = (const float*)d_in[4];
    const float* b1  = (const float*)d_in[5];
    const float* W2  = (const float*)d_in[6];
    const float* as2 = (const float*)d_in[7];
    const float* ad2 = (const float*)d_in[8];
    const float* b2  = (const float*)d_in[9];
    float* out = (float*)d_out;

    const int SM1 = (16384 + 32 * 129) * 4;  // 82048 B
    const int SM2 = (5120 + 64 * 129) * 4;   // 53504 B
    cudaFuncSetAttribute(gemm1_kernel, cudaFuncAttributeMaxDynamicSharedMemorySize, SM1);
    cudaFuncSetAttribute(gemm2_kernel, cudaFuncAttributeMaxDynamicSharedMemorySize, SM2);

    void* p;
    cudaGetSymbolAddress(&p, g_dn1); cudaMemsetAsync(p, 0, sizeof(float) * NN * 8);
    cudaGetSymbolAddress(&p, g_o1);  cudaMemsetAsync(p, 0, sizeof(float) * NN * 128);
    cudaGetSymbolAddress(&p, g_dn2); cudaMemsetAsync(p, 0, sizeof(float) * NN);
    cudaMemsetAsync(out, 0, sizeof(float) * NN * 40);

    repack<<<(ET + 255) / 256, 256>>>(ei);
    gemm1_kernel<<<NN / 32, 256, SM1>>>(x, W1, as1, ad1);
    l1_denom<<<(ET + 255) / 256, 256>>>();
    l1_agg<<<(ET + 7) / 8, 256>>>();
    bias_elu<<<(NN * 128 + 255) / 256, 256>>>(b1);
    gemm2_kernel<<<(NN + 63) / 64, 160, SM2>>>(W2);
    a2_kernel<<<(NN + 7) / 8, 256>>>(as2, ad2);
    l2_denom<<<(ET + 255) / 256, 256>>>();
    l2_agg<<<(ET + 7) / 8, 256>>>(out);
    lsm_kernel<<<(NN + 7) / 8, 256>>>(out, b2);
}

// round 3
// speedup vs baseline: 1.6436x; 1.6436x over previous
#include <cuda_runtime.h>

#define NN 100000
#define NE 1600000
#define ET (NE + NN)
#define NB 98   // ceil(NN/1024) scan blocks

// -------- scratch (device globals: no allocations allowed) --------
__device__ int   g_src[ET];
__device__ int   g_dst[ET];
__device__ int   g_col[ET];       // CSR column (src) indices, sorted by dst
__device__ int   g_deg[NN];
__device__ int   g_scan[NN];
__device__ int   g_bsum[NB];
__device__ int   g_boff[NB];
__device__ int   g_rp[NN + 1];    // CSR row pointers
__device__ int   g_cur[NN];       // scatter cursors
__device__ float g_h1[NN * 128];  // layer1 features [N,8,16]
__device__ float g_as1[NN * 8];
__device__ float g_ad1[NN * 8];
__device__ float g_o1[NN * 128];  // layer1 out (bias+elu applied) = h2
__device__ float g_z[NN * 40];    // layer2 features
__device__ float g_as2[NN];
__device__ float g_ad2[NN];

__device__ __forceinline__ float lrelu(float v) { return v > 0.f ? v : 0.2f * v; }

// ==================== repack edges (dtype-robust) + self loops + histogram ====================
__global__ void repack_hist(const int* __restrict__ e32) {
    __shared__ int is64;
    if (threadIdx.x == 0) {
        int z = 0;
#pragma unroll
        for (int j = 1; j <= 16; j++) z |= e32[2 * j + 1];
        is64 = (z == 0) ? 1 : 0;
    }
    __syncthreads();
    int i = blockIdx.x * blockDim.x + threadIdx.x;
    if (i >= ET) return;
    int s, d;
    if (i < NE) {
        if (is64) { s = e32[2 * i]; d = e32[2 * (NE + i)]; }
        else      { s = e32[i];     d = e32[NE + i]; }
    } else {
        s = d = i - NE;
    }
    g_src[i] = s;
    g_dst[i] = d;
    atomicAdd(&g_deg[d], 1);
}

// ==================== scan (3 stages) ====================
__global__ void scan1() {
    __shared__ int sm[1024];
    int i = blockIdx.x * 1024 + threadIdx.x;
    int v = (i < NN) ? g_deg[i] : 0;
    sm[threadIdx.x] = v;
    __syncthreads();
    for (int off = 1; off < 1024; off <<= 1) {
        int t = (threadIdx.x >= off) ? sm[threadIdx.x - off] : 0;
        __syncthreads();
        sm[threadIdx.x] += t;
        __syncthreads();
    }
    if (i < NN) g_scan[i] = sm[threadIdx.x];
    if (threadIdx.x == 1023) g_bsum[blockIdx.x] = sm[1023];
}

__global__ void scan2() {
    if (threadIdx.x == 0) {
        int run = 0;
        for (int b = 0; b < NB; b++) { g_boff[b] = run; run += g_bsum[b]; }
    }
}

__global__ void scan3() {
    int i = blockIdx.x * blockDim.x + threadIdx.x;
    if (i >= NN) return;
    int incl = g_scan[i] + g_boff[i >> 10];
    g_rp[i + 1] = incl;
    g_cur[i] = incl - g_deg[i];
    if (i == 0) g_rp[0] = 0;
}

__global__ void scatter() {
    int i = blockIdx.x * blockDim.x + threadIdx.x;
    if (i >= ET) return;
    int d = g_dst[i];
    int pos = atomicAdd(&g_cur[d], 1);
    g_col[pos] = g_src[i];
}

// ==================== GEMM1: h1 = x @ W1, + attention dots ====================
__global__ void gemm1_kernel(const float* __restrict__ x, const float* __restrict__ W,
                             const float* __restrict__ atts, const float* __restrict__ attd) {
    extern __shared__ float sm[];
    float* Ws = sm;           // 128*128
    float* xs = sm + 16384;   // 32*129
    int t = threadIdx.x;
    int ct = t & 31, rt = t >> 5;
    int row0 = blockIdx.x * 32;

    for (int i = t; i < 16384; i += 256) Ws[i] = W[i];
    for (int i = t; i < 4096; i += 256) {
        int r = i >> 7, k = i & 127;
        xs[r * 129 + k] = x[(row0 + r) * 128 + k];
    }
    __syncthreads();

    float acc[4][4] = {};
#pragma unroll 4
    for (int k = 0; k < 128; k++) {
        float4 w = *(const float4*)&Ws[k * 128 + 4 * ct];
#pragma unroll
        for (int i = 0; i < 4; i++) {
            float xv = xs[(rt * 4 + i) * 129 + k];
            acc[i][0] += xv * w.x; acc[i][1] += xv * w.y;
            acc[i][2] += xv * w.z; acc[i][3] += xv * w.w;
        }
    }

    float4 avs = *(const float4*)&atts[4 * ct];
    float4 avd = *(const float4*)&attd[4 * ct];
#pragma unroll
    for (int i = 0; i < 4; i++) {
        int row = row0 + rt * 4 + i;
        *(float4*)&g_h1[row * 128 + 4 * ct] =
            make_float4(acc[i][0], acc[i][1], acc[i][2], acc[i][3]);
        float ps = acc[i][0] * avs.x + acc[i][1] * avs.y + acc[i][2] * avs.z + acc[i][3] * avs.w;
        float pd = acc[i][0] * avd.x + acc[i][1] * avd.y + acc[i][2] * avd.z + acc[i][3] * avd.w;
        ps += __shfl_xor_sync(0xffffffffu, ps, 1);
        ps += __shfl_xor_sync(0xffffffffu, ps, 2);
        pd += __shfl_xor_sync(0xffffffffu, pd, 1);
        pd += __shfl_xor_sync(0xffffffffu, pd, 2);
        if ((ct & 3) == 0) {
            g_as1[row * 8 + (ct >> 2)] = ps;
            g_ad1[row * 8 + (ct >> 2)] = pd;
        }
    }
}

// ==================== fused layer1: denom + aggregate + bias + ELU ====================
// warp per destination node; lane owns cols lane*4..lane*4+3 (head = lane/4).
__global__ void l1_gather(const float* __restrict__ b1) {
    int w = (blockIdx.x * blockDim.x + threadIdx.x) >> 5;
    int lane = threadIdx.x & 31;
    if (w >= NN) return;
    int beg = g_rp[w], end = g_rp[w + 1];

    float ad[8];
#pragma unroll
    for (int h = 0; h < 8; h++) ad[h] = g_ad1[w * 8 + h];

    // pass 1: softmax denominators (lane-parallel over edges)
    float dn[8] = {};
    for (int e = beg + lane; e < end; e += 32) {
        int s = g_col[e];
        float4 s0 = *(const float4*)&g_as1[s * 8];
        float4 s1 = *(const float4*)&g_as1[s * 8 + 4];
        dn[0] += __expf(lrelu(s0.x + ad[0]));
        dn[1] += __expf(lrelu(s0.y + ad[1]));
        dn[2] += __expf(lrelu(s0.z + ad[2]));
        dn[3] += __expf(lrelu(s0.w + ad[3]));
        dn[4] += __expf(lrelu(s1.x + ad[4]));
        dn[5] += __expf(lrelu(s1.y + ad[5]));
        dn[6] += __expf(lrelu(s1.z + ad[6]));
        dn[7] += __expf(lrelu(s1.w + ad[7]));
    }
#pragma unroll
    for (int h = 0; h < 8; h++)
        for (int off = 16; off; off >>= 1)
            dn[h] += __shfl_xor_sync(0xffffffffu, dn[h], off);

    int h = lane >> 2;
    float adh = ad[h];
    float rdn = 1.f / (dn[h] + 1e-16f);

    // pass 2: weighted gather, coalesced 512B rows
    float4 acc = make_float4(0.f, 0.f, 0.f, 0.f);
    for (int base = beg; base < end; base += 32) {
        int idx = base + lane;
        int sc = (idx < end) ? g_col[idx] : 0;
        int n = min(32, end - base);
        for (int j = 0; j < n; j++) {
            int s = __shfl_sync(0xffffffffu, sc, j);
            float a = __expf(lrelu(g_as1[s * 8 + h] + adh)) * rdn;
            float4 v = *(const float4*)&g_h1[s * 128 + lane * 4];
            acc.x += a * v.x; acc.y += a * v.y;
            acc.z += a * v.z; acc.w += a * v.w;
        }
    }

    // epilogue: bias + ELU
    float4 bb = *(const float4*)&b1[lane * 4];
    acc.x += bb.x; acc.y += bb.y; acc.z += bb.z; acc.w += bb.w;
    acc.x = acc.x > 0.f ? acc.x : expm1f(acc.x);
    acc.y = acc.y > 0.f ? acc.y : expm1f(acc.y);
    acc.z = acc.z > 0.f ? acc.z : expm1f(acc.z);
    acc.w = acc.w > 0.f ? acc.w : expm1f(acc.w);
    *(float4*)&g_o1[w * 128 + lane * 4] = acc;
}

// ==================== GEMM2: z = h2 @ W2 (128 -> 40) ====================
__global__ void gemm2_kernel(const float* __restrict__ W) {
    extern __shared__ float sm[];
    float* Ws = sm;           // 128*40
    float* xs = sm + 5120;    // 64*129
    int t = threadIdx.x;
    int ct = t % 10, rt = t / 10;
    int row0 = blockIdx.x * 64;

    for (int i = t; i < 5120; i += 160) Ws[i] = W[i];
    for (int i = t; i < 8192; i += 160) {
        int r = i >> 7, k = i & 127;
        int row = row0 + r;
        xs[r * 129 + k] = (row < NN) ? g_o1[row * 128 + k] : 0.f;
    }
    __syncthreads();

    float acc[4][4] = {};
#pragma unroll 2
    for (int k = 0; k < 128; k++) {
        float4 w = *(const float4*)&Ws[k * 40 + 4 * ct];
#pragma unroll
        for (int i = 0; i < 4; i++) {
            float xv = xs[(rt * 4 + i) * 129 + k];
            acc[i][0] += xv * w.x; acc[i][1] += xv * w.y;
            acc[i][2] += xv * w.z; acc[i][3] += xv * w.w;
        }
    }
#pragma unroll
    for (int i = 0; i < 4; i++) {
        int row = row0 + rt * 4 + i;
        if (row < NN)
            *(float4*)&g_z[row * 40 + 4 * ct] =
                make_float4(acc[i][0], acc[i][1], acc[i][2], acc[i][3]);
    }
}

// ==================== layer2 attention dots (warp per row) ====================
__global__ void a2_kernel(const float* __restrict__ atts, const float* __restrict__ attd) {
    int w = (blockIdx.x * blockDim.x + threadIdx.x) >> 5;
    int lane = threadIdx.x & 31;
    if (w >= NN) return;
    float ps = 0.f, pd = 0.f;
    for (int c = lane; c < 40; c += 32) {
        float v = g_z[w * 40 + c];
        ps += v * atts[c];
        pd += v * attd[c];
    }
    for (int o = 16; o; o >>= 1) {
        ps += __shfl_xor_sync(0xffffffffu, ps, o);
        pd += __shfl_xor_sync(0xffffffffu, pd, o);
    }
    if (lane == 0) { g_as2[w] = ps; g_ad2[w] = pd; }
}

// ==================== fused layer2: denom + aggregate + bias + log_softmax ====================
__global__ void l2_gather(float* __restrict__ out, const float* __restrict__ b2) {
    int w = (blockIdx.x * blockDim.x + threadIdx.x) >> 5;
    int lane = threadIdx.x & 31;
    if (w >= NN) return;
    int beg = g_rp[w], end = g_rp[w + 1];
    float adw = g_ad2[w];

    float dn = 0.f;
    for (int e = beg + lane; e < end; e += 32)
        dn += __expf(lrelu(g_as2[g_col[e]] + adw));
    for (int off = 16; off; off >>= 1)
        dn += __shfl_xor_sync(0xffffffffu, dn, off);
    float rdn = 1.f / (dn + 1e-16f);

    float a1 = 0.f, a2 = 0.f;
    for (int base = beg; base < end; base += 32) {
        int idx = base + lane;
        int sc = (idx < end) ? g_col[idx] : 0;
        int n = min(32, end - base);
        for (int j = 0; j < n; j++) {
            int s = __shfl_sync(0xffffffffu, sc, j);
            float al = __expf(lrelu(g_as2[s] + adw)) * rdn;
            a1 += al * g_z[s * 40 + lane];
            if (lane < 8) a2 += al * g_z[s * 40 + 32 + lane];
        }
    }

    float v1 = a1 + b2[lane];
    float v2 = (lane < 8) ? a2 + b2[32 + lane] : -1e30f;
    float m = fmaxf(v1, v2);
    for (int o = 16; o; o >>= 1) m = fmaxf(m, __shfl_xor_sync(0xffffffffu, m, o));
    float s = expf(v1 - m) + ((lane < 8) ? expf(v2 - m) : 0.f);
    for (int o = 16; o; o >>= 1) s += __shfl_xor_sync(0xffffffffu, s, o);
    float ls = m + logf(s);
    out[w * 40 + lane] = v1 - ls;
    if (lane < 8) out[w * 40 + 32 + lane] = v2 - ls;
}

// ==================== launch ====================
extern "C" void kernel_launch(void* const* d_in, const int* in_sizes, int n_in,
                              void* d_out, int out_size) {
    const float* x   = (const float*)d_in[0];
    const int*   ei  = (const int*)d_in[1];
    const float* W1  = (const float*)d_in[2];
    const float* as1 = (const float*)d_in[3];
    const float* ad1 = (const float*)d_in[4];
    const float* b1  = (const float*)d_in[5];
    const float* W2  = (const float*)d_in[6];
    const float* as2 = (const float*)d_in[7];
    const float* ad2 = (const float*)d_in[8];
    const float* b2  = (const float*)d_in[9];
    float* out = (float*)d_out;

    const int SM1 = (16384 + 32 * 129) * 4;
    const int SM2 = (5120 + 64 * 129) * 4;
    cudaFuncSetAttribute(gemm1_kernel, cudaFuncAttributeMaxDynamicSharedMemorySize, SM1);
    cudaFuncSetAttribute(gemm2_kernel, cudaFuncAttributeMaxDynamicSharedMemorySize, SM2);

    void* p;
    cudaGetSymbolAddress(&p, g_deg);
    cudaMemsetAsync(p, 0, sizeof(int) * NN);

    repack_hist<<<(ET + 255) / 256, 256>>>(ei);
    scan1<<<NB, 1024>>>();
    scan2<<<1, 32>>>();
    scan3<<<(NN + 255) / 256, 256>>>();
    scatter<<<(ET + 255) / 256, 256>>>();

    gemm1_kernel<<<NN / 32, 256, SM1>>>(x, W1, as1, ad1);
    l1_gather<<<(NN * 32 + 255) / 256, 256>>>(b1);
    gemm2_kernel<<<(NN + 63) / 64, 160, SM2>>>(W2);
    a2_kernel<<<(NN + 7) / 8, 256>>>(as2, ad2);
    l2_gather<<<(NN * 32 + 255) / 256, 256>>>(out, b2);
}

// round 4
// speedup vs baseline: 1.9145x; 1.1648x over previous
#include <cuda_runtime.h>

#define NN 100000
#define NE 1600000
#define ET (NE + NN)
#define NB 98   // ceil(NN/1024) scan blocks

// -------- scratch (device globals: no allocations allowed) --------
__device__ int   g_col[ET];       // CSR column (src) indices, sorted by dst
__device__ int   g_deg[NN];
__device__ int   g_scan[NN];
__device__ int   g_bsum[NB];
__device__ int   g_boff[NB];
__device__ int   g_rp[NN + 1];    // CSR row pointers
__device__ int   g_cur[NN];       // scatter cursors
__device__ float g_h1[NN * 128];  // layer1 features [N,8,16]
__device__ float g_as1[NN * 8];
__device__ float g_ad1[NN * 8];
__device__ float g_o1[NN * 128];  // layer1 out (bias+elu applied) = h2
__device__ float g_z[NN * 40];    // layer2 features
__device__ float g_as2[NN];
__device__ float g_ad2[NN];

__device__ __forceinline__ float lrelu(float v) { return v > 0.f ? v : 0.2f * v; }

// int64-vs-int32 probe: for little-endian int64 indices the odd 32-bit words of
// the first entries are zero high-words; for int32 data they are random indices.
__device__ __forceinline__ int detect64(const int* e32) {
    int z = 0;
#pragma unroll
    for (int j = 1; j <= 16; j++) z |= e32[2 * j + 1];
    return (z == 0) ? 1 : 0;
}

// ==================== CSR build ====================
__global__ void hist_kernel(const int* __restrict__ e32) {
    __shared__ int is64;
    if (threadIdx.x == 0) is64 = detect64(e32);
    __syncthreads();
    int i = blockIdx.x * blockDim.x + threadIdx.x;
    if (i >= ET) return;
    int d;
    if (i < NE) d = is64 ? e32[2 * (NE + i)] : e32[NE + i];
    else        d = i - NE;
    atomicAdd(&g_deg[d], 1);
}

__global__ void scan1() {
    __shared__ int sm[1024];
    int i = blockIdx.x * 1024 + threadIdx.x;
    int v = (i < NN) ? g_deg[i] : 0;
    sm[threadIdx.x] = v;
    __syncthreads();
    for (int off = 1; off < 1024; off <<= 1) {
        int t = (threadIdx.x >= off) ? sm[threadIdx.x - off] : 0;
        __syncthreads();
        sm[threadIdx.x] += t;
        __syncthreads();
    }
    if (i < NN) g_scan[i] = sm[threadIdx.x];
    if (threadIdx.x == 1023) g_bsum[blockIdx.x] = sm[1023];
}

__global__ void scan2() {
    __shared__ int sm[128];
    int t = threadIdx.x;
    int v = (t < NB) ? g_bsum[t] : 0;
    sm[t] = v;
    __syncthreads();
    for (int off = 1; off < 128; off <<= 1) {
        int a = (t >= off) ? sm[t - off] : 0;
        __syncthreads();
        sm[t] += a;
        __syncthreads();
    }
    if (t < NB) g_boff[t] = sm[t] - v;   // exclusive
}

__global__ void scan3() {
    int i = blockIdx.x * blockDim.x + threadIdx.x;
    if (i >= NN) return;
    int incl = g_scan[i] + g_boff[i >> 10];
    g_rp[i + 1] = incl;
    g_cur[i] = incl - g_deg[i];
    if (i == 0) g_rp[0] = 0;
}

__global__ void scatter(const int* __restrict__ e32) {
    __shared__ int is64;
    if (threadIdx.x == 0) is64 = detect64(e32);
    __syncthreads();
    int i = blockIdx.x * blockDim.x + threadIdx.x;
    if (i >= ET) return;
    int s, d;
    if (i < NE) {
        if (is64) { s = e32[2 * i]; d = e32[2 * (NE + i)]; }
        else      { s = e32[i];     d = e32[NE + i]; }
    } else {
        s = d = i - NE;
    }
    int pos = atomicAdd(&g_cur[d], 1);
    g_col[pos] = s;
}

// ==================== GEMM1: h1 = x @ W1, + attention dots ====================
// block: 256 threads, 64 rows, 8 rows x 4 cols per thread.
__global__ void gemm1_kernel(const float* __restrict__ x, const float* __restrict__ W,
                             const float* __restrict__ atts, const float* __restrict__ attd) {
    extern __shared__ float sm[];
    float* Ws = sm;           // 128*128 = 16384
    float* xs = sm + 16384;   // 64*129 = 8256
    int t = threadIdx.x;
    int ct = t & 31, rt = t >> 5;   // 8 warps, warp rt handles rows rt*8..rt*8+7
    int row0 = blockIdx.x * 64;

    for (int i = t; i < 16384; i += 256) Ws[i] = W[i];
    for (int i = t; i < 8192; i += 256) {
        int r = i >> 7, k = i & 127;
        int row = row0 + r;
        xs[r * 129 + k] = (row < NN) ? x[row * 128 + k] : 0.f;
    }
    __syncthreads();

    float acc[8][4] = {};
#pragma unroll 2
    for (int k = 0; k < 128; k++) {
        float4 w = *(const float4*)&Ws[k * 128 + 4 * ct];
#pragma unroll
        for (int i = 0; i < 8; i++) {
            float xv = xs[(rt * 8 + i) * 129 + k];
            acc[i][0] += xv * w.x; acc[i][1] += xv * w.y;
            acc[i][2] += xv * w.z; acc[i][3] += xv * w.w;
        }
    }

    float4 avs = *(const float4*)&atts[4 * ct];
    float4 avd = *(const float4*)&attd[4 * ct];
#pragma unroll
    for (int i = 0; i < 8; i++) {
        int row = row0 + rt * 8 + i;   // uniform across warp
        if (row < NN) {
            *(float4*)&g_h1[row * 128 + 4 * ct] =
                make_float4(acc[i][0], acc[i][1], acc[i][2], acc[i][3]);
            float ps = acc[i][0] * avs.x + acc[i][1] * avs.y + acc[i][2] * avs.z + acc[i][3] * avs.w;
            float pd = acc[i][0] * avd.x + acc[i][1] * avd.y + acc[i][2] * avd.z + acc[i][3] * avd.w;
            ps += __shfl_xor_sync(0xffffffffu, ps, 1);
            ps += __shfl_xor_sync(0xffffffffu, ps, 2);
            pd += __shfl_xor_sync(0xffffffffu, pd, 1);
            pd += __shfl_xor_sync(0xffffffffu, pd, 2);
            if ((ct & 3) == 0) {
                g_as1[row * 8 + (ct >> 2)] = ps;
                g_ad1[row * 8 + (ct >> 2)] = pd;
            }
        }
    }
}

// ==================== fused layer1: denom + aggregate + bias + ELU ====================
__global__ void l1_gather(const float* __restrict__ b1) {
    int w = (blockIdx.x * blockDim.x + threadIdx.x) >> 5;
    int lane = threadIdx.x & 31;
    if (w >= NN) return;
    int beg = g_rp[w], end = g_rp[w + 1];

    float ad[8];
#pragma unroll
    for (int h = 0; h < 8; h++) ad[h] = g_ad1[w * 8 + h];

    float dn[8] = {};
    for (int e = beg + lane; e < end; e += 32) {
        int s = g_col[e];
        float4 s0 = *(const float4*)&g_as1[s * 8];
        float4 s1 = *(const float4*)&g_as1[s * 8 + 4];
        dn[0] += __expf(lrelu(s0.x + ad[0]));
        dn[1] += __expf(lrelu(s0.y + ad[1]));
        dn[2] += __expf(lrelu(s0.z + ad[2]));
        dn[3] += __expf(lrelu(s0.w + ad[3]));
        dn[4] += __expf(lrelu(s1.x + ad[4]));
        dn[5] += __expf(lrelu(s1.y + ad[5]));
        dn[6] += __expf(lrelu(s1.z + ad[6]));
        dn[7] += __expf(lrelu(s1.w + ad[7]));
    }
#pragma unroll
    for (int h = 0; h < 8; h++)
        for (int off = 16; off; off >>= 1)
            dn[h] += __shfl_xor_sync(0xffffffffu, dn[h], off);

    int h = lane >> 2;
    float adh = ad[h];
    float rdn = 1.f / (dn[h] + 1e-16f);

    float4 acc = make_float4(0.f, 0.f, 0.f, 0.f);
    for (int base = beg; base < end; base += 32) {
        int idx = base + lane;
        int sc = (idx < end) ? g_col[idx] : 0;
        int n = min(32, end - base);
#pragma unroll 4
        for (int j = 0; j < n; j++) {
            int s = __shfl_sync(0xffffffffu, sc, j);
            float a = __expf(lrelu(g_as1[s * 8 + h] + adh)) * rdn;
            float4 v = *(const float4*)&g_h1[s * 128 + lane * 4];
            acc.x += a * v.x; acc.y += a * v.y;
            acc.z += a * v.z; acc.w += a * v.w;
        }
    }

    float4 bb = *(const float4*)&b1[lane * 4];
    acc.x += bb.x; acc.y += bb.y; acc.z += bb.z; acc.w += bb.w;
    acc.x = acc.x > 0.f ? acc.x : expm1f(acc.x);
    acc.y = acc.y > 0.f ? acc.y : expm1f(acc.y);
    acc.z = acc.z > 0.f ? acc.z : expm1f(acc.z);
    acc.w = acc.w > 0.f ? acc.w : expm1f(acc.w);
    *(float4*)&g_o1[w * 128 + lane * 4] = acc;
}

// ==================== GEMM2 (128->40) with fused a2 attention dots ====================
__global__ void gemm2_kernel(const float* __restrict__ W,
                             const float* __restrict__ atts, const float* __restrict__ attd) {
    extern __shared__ float sm[];
    float* Ws = sm;                  // 5120
    float* xs = sm + 5120;           // 64*129 = 8256
    float* sa = sm + 5120 + 8256;    // 64
    float* sd = sa + 64;             // 64
    int t = threadIdx.x;
    int ct = t % 10, rt = t / 10;
    int row0 = blockIdx.x * 64;

    for (int i = t; i < 5120; i += 160) Ws[i] = W[i];
    for (int i = t; i < 8192; i += 160) {
        int r = i >> 7, k = i & 127;
        int row = row0 + r;
        xs[r * 129 + k] = (row < NN) ? g_o1[row * 128 + k] : 0.f;
    }
    if (t < 64) { sa[t] = 0.f; sd[t] = 0.f; }
    __syncthreads();

    float acc[4][4] = {};
#pragma unroll 2
    for (int k = 0; k < 128; k++) {
        float4 w = *(const float4*)&Ws[k * 40 + 4 * ct];
#pragma unroll
        for (int i = 0; i < 4; i++) {
            float xv = xs[(rt * 4 + i) * 129 + k];
            acc[i][0] += xv * w.x; acc[i][1] += xv * w.y;
            acc[i][2] += xv * w.z; acc[i][3] += xv * w.w;
        }
    }

    float4 avs = *(const float4*)&atts[4 * ct];
    float4 avd = *(const float4*)&attd[4 * ct];
#pragma unroll
    for (int i = 0; i < 4; i++) {
        int row = row0 + rt * 4 + i;
        if (row < NN)
            *(float4*)&g_z[row * 40 + 4 * ct] =
                make_float4(acc[i][0], acc[i][1], acc[i][2], acc[i][3]);
        float ps = acc[i][0] * avs.x + acc[i][1] * avs.y + acc[i][2] * avs.z + acc[i][3] * avs.w;
        float pd = acc[i][0] * avd.x + acc[i][1] * avd.y + acc[i][2] * avd.z + acc[i][3] * avd.w;
        atomicAdd(&sa[rt * 4 + i], ps);
        atomicAdd(&sd[rt * 4 + i], pd);
    }
    __syncthreads();
    if (t < 64) {
        int row = row0 + t;
        if (row < NN) { g_as2[row] = sa[t]; g_ad2[row] = sd[t]; }
    }
}

// ==================== fused layer2: denom + aggregate + bias + log_softmax ====================
__global__ void l2_gather(float* __restrict__ out, const float* __restrict__ b2) {
    int w = (blockIdx.x * blockDim.x + threadIdx.x) >> 5;
    int lane = threadIdx.x & 31;
    if (w >= NN) return;
    int beg = g_rp[w], end = g_rp[w + 1];
    float adw = g_ad2[w];

    float dn = 0.f;
    for (int e = beg + lane; e < end; e += 32)
        dn += __expf(lrelu(g_as2[g_col[e]] + adw));
    for (int off = 16; off; off >>= 1)
        dn += __shfl_xor_sync(0xffffffffu, dn, off);
    float rdn = 1.f / (dn + 1e-16f);

    float a1 = 0.f, a2 = 0.f;
    for (int base = beg; base < end; base += 32) {
        int idx = base + lane;
        int sc = (idx < end) ? g_col[idx] : 0;
        int n = min(32, end - base);
#pragma unroll 4
        for (int j = 0; j < n; j++) {
            int s = __shfl_sync(0xffffffffu, sc, j);
            float al = __expf(lrelu(g_as2[s] + adw)) * rdn;
            a1 += al * g_z[s * 40 + lane];
            if (lane < 8) a2 += al * g_z[s * 40 + 32 + lane];
        }
    }

    float v1 = a1 + b2[lane];
    float v2 = (lane < 8) ? a2 + b2[32 + lane] : -1e30f;
    float m = fmaxf(v1, v2);
    for (int o = 16; o; o >>= 1) m = fmaxf(m, __shfl_xor_sync(0xffffffffu, m, o));
    float s = expf(v1 - m) + ((lane < 8) ? expf(v2 - m) : 0.f);
    for (int o = 16; o; o >>= 1) s += __shfl_xor_sync(0xffffffffu, s, o);
    float ls = m + logf(s);
    out[w * 40 + lane] = v1 - ls;
    if (lane < 8) out[w * 40 + 32 + lane] = v2 - ls;
}

// ==================== launch ====================
extern "C" void kernel_launch(void* const* d_in, const int* in_sizes, int n_in,
                              void* d_out, int out_size) {
    const float* x   = (const float*)d_in[0];
    const int*   ei  = (const int*)d_in[1];
    const float* W1  = (const float*)d_in[2];
    const float* as1 = (const float*)d_in[3];
    const float* ad1 = (const float*)d_in[4];
    const float* b1  = (const float*)d_in[5];
    const float* W2  = (const float*)d_in[6];
    const float* as2 = (const float*)d_in[7];
    const float* ad2 = (const float*)d_in[8];
    const float* b2  = (const float*)d_in[9];
    float* out = (float*)d_out;

    // fork-join resources (created once, on the uncaptured correctness call)
    static cudaStream_t sB = nullptr;
    static cudaEvent_t evF = nullptr, evJ = nullptr;
    if (!sB) {
        cudaStreamCreateWithFlags(&sB, cudaStreamNonBlocking);
        cudaEventCreateWithFlags(&evF, cudaEventDisableTiming);
        cudaEventCreateWithFlags(&evJ, cudaEventDisableTiming);
    }

    const int SM1 = (16384 + 64 * 129) * 4;        // 98560 B
    const int SM2 = (5120 + 64 * 129 + 128) * 4;   // 54016 B
    cudaFuncSetAttribute(gemm1_kernel, cudaFuncAttributeMaxDynamicSharedMemorySize, SM1);
    cudaFuncSetAttribute(gemm2_kernel, cudaFuncAttributeMaxDynamicSharedMemorySize, SM2);

    // fork: CSR build on side stream, gemm1 on main stream
    cudaEventRecord(evF, 0);
    cudaStreamWaitEvent(sB, evF, 0);

    void* p;
    cudaGetSymbolAddress(&p, g_deg);
    cudaMemsetAsync(p, 0, sizeof(int) * NN, sB);
    hist_kernel<<<(ET + 255) / 256, 256, 0, sB>>>(ei);
    scan1<<<NB, 1024, 0, sB>>>();
    scan2<<<1, 128, 0, sB>>>();
    scan3<<<(NN + 255) / 256, 256, 0, sB>>>();
    scatter<<<(ET + 255) / 256, 256, 0, sB>>>(ei);
    cudaEventRecord(evJ, sB);

    gemm1_kernel<<<(NN + 63) / 64, 256, SM1>>>(x, W1, as1, ad1);

    // join
    cudaStreamWaitEvent(0, evJ, 0);

    l1_gather<<<(NN * 32 + 255) / 256, 256>>>(b1);
    gemm2_kernel<<<(NN + 63) / 64, 160, SM2>>>(W2, as2, ad2);
    l2_gather<<<(NN * 32 + 255) / 256, 256>>>(out, b2);
}

// round 5
// speedup vs baseline: 1.9413x; 1.0140x over previous
#include <cuda_runtime.h>

#define NN 100000
#define NE 1600000
#define ET (NE + NN)
#define NB 98   // ceil(NN/1024) scan blocks

typedef unsigned long long u64;

// -------- scratch (device globals: no allocations allowed) --------
__device__ int   g_col[ET];       // CSR column (src) indices, sorted by dst
__device__ int   g_deg[NN];       // zeroed at end of scatter for next replay
__device__ int   g_scan[NN];
__device__ int   g_bsum[NB];
__device__ int   g_boff[NB];
__device__ int   g_rp[NN + 1];    // CSR row pointers
__device__ int   g_cur[NN];       // scatter cursors
__device__ float g_h1[NN * 128];  // layer1 features [N,8,16]
__device__ float g_as1[NN * 8];
__device__ float g_ad1[NN * 8];
__device__ float g_o1[NN * 128];  // layer1 out (bias+elu applied) = h2
__device__ float g_z[NN * 40];    // layer2 features
__device__ float g_as2[NN];
__device__ float g_ad2[NN];

__device__ __forceinline__ float lrelu(float v) { return v > 0.f ? v : 0.2f * v; }

__device__ __forceinline__ u64 pk2(float lo, float hi) {
    u64 r; asm("mov.b64 %0, {%1, %2};" : "=l"(r) : "f"(lo), "f"(hi)); return r;
}
__device__ __forceinline__ void upk2(float& lo, float& hi, u64 v) {
    asm("mov.b64 {%0, %1}, %2;" : "=f"(lo), "=f"(hi) : "l"(v));
}
__device__ __forceinline__ void ffma2(u64& d, u64 a, u64 b) {
    asm("fma.rn.f32x2 %0, %1, %2, %0;" : "+l"(d) : "l"(a), "l"(b));
}

// int64-vs-int32 probe: for little-endian int64 indices the odd 32-bit words of
// the first entries are zero high-words; for int32 data they are random indices.
__device__ __forceinline__ int detect64(const int* e32) {
    int z = 0;
#pragma unroll
    for (int j = 1; j <= 16; j++) z |= e32[2 * j + 1];
    return (z == 0) ? 1 : 0;
}

// ==================== CSR build ====================
__global__ void hist_kernel(const int* __restrict__ e32) {
    __shared__ int is64;
    if (threadIdx.x == 0) is64 = detect64(e32);
    __syncthreads();
    int i = blockIdx.x * blockDim.x + threadIdx.x;
    if (i >= ET) return;
    int d;
    if (i < NE) d = is64 ? e32[2 * (NE + i)] : e32[NE + i];
    else        d = i - NE;
    atomicAdd(&g_deg[d], 1);
}

__global__ void scan1() {
    __shared__ int sm[1024];
    int i = blockIdx.x * 1024 + threadIdx.x;
    int v = (i < NN) ? g_deg[i] : 0;
    sm[threadIdx.x] = v;
    __syncthreads();
    for (int off = 1; off < 1024; off <<= 1) {
        int t = (threadIdx.x >= off) ? sm[threadIdx.x - off] : 0;
        __syncthreads();
        sm[threadIdx.x] += t;
        __syncthreads();
    }
    if (i < NN) g_scan[i] = sm[threadIdx.x];
    if (threadIdx.x == 1023) g_bsum[blockIdx.x] = sm[1023];
}

__global__ void scan2() {
    __shared__ int sm[128];
    int t = threadIdx.x;
    int v = (t < NB) ? g_bsum[t] : 0;
    sm[t] = v;
    __syncthreads();
    for (int off = 1; off < 128; off <<= 1) {
        int a = (t >= off) ? sm[t - off] : 0;
        __syncthreads();
        sm[t] += a;
        __syncthreads();
    }
    if (t < NB) g_boff[t] = sm[t] - v;   // exclusive
}

__global__ void scan3() {
    int i = blockIdx.x * blockDim.x + threadIdx.x;
    if (i >= NN) return;
    int incl = g_scan[i] + g_boff[i >> 10];
    g_rp[i + 1] = incl;
    g_cur[i] = incl - g_deg[i];
    if (i == 0) g_rp[0] = 0;
}

__global__ void scatter(const int* __restrict__ e32) {
    __shared__ int is64;
    if (threadIdx.x == 0) is64 = detect64(e32);
    __syncthreads();
    int i = blockIdx.x * blockDim.x + threadIdx.x;
    if (i < NN) g_deg[i] = 0;   // reset for next graph replay (deg already consumed)
    if (i >= ET) return;
    int s, d;
    if (i < NE) {
        if (is64) { s = e32[2 * i]; d = e32[2 * (NE + i)]; }
        else      { s = e32[i];     d = e32[NE + i]; }
    } else {
        s = d = i - NE;
    }
    int pos = atomicAdd(&g_cur[d], 1);
    g_col[pos] = s;
}

// ==================== GEMM1: h1 = x @ W1 (f32x2), + attention dots ====================
// block: 256 threads, 64 rows, 8 rows x 4 cols per thread; K packed in pairs.
__global__ void gemm1_kernel(const float* __restrict__ x, const float* __restrict__ W,
                             const float* __restrict__ atts, const float* __restrict__ attd) {
    extern __shared__ float sm[];
    float* Ws = sm;            // 128*128 = 16384
    float* xs = sm + 16384;    // 64*132 = 8448 (132: 8B-aligned b64 k-pairs)
    int t = threadIdx.x;
    int ct = t & 31, rt = t >> 5;
    int row0 = blockIdx.x * 64;

    for (int i = t; i < 4096; i += 256)          // Ws via float4
        *(float4*)&Ws[i * 4] = *(const float4*)&W[i * 4];
    for (int i = t; i < 2048; i += 256) {        // xs via float4
        int r = i >> 5, k4 = (i & 31) * 4;
        int row = row0 + r;
        float4 v = (row < NN) ? *(const float4*)&x[row * 128 + k4]
                              : make_float4(0.f, 0.f, 0.f, 0.f);
        *(float4*)&xs[r * 132 + k4] = v;
    }
    __syncthreads();

    u64 acc2[8][4];
#pragma unroll
    for (int i = 0; i < 8; i++)
#pragma unroll
        for (int c = 0; c < 4; c++) acc2[i][c] = 0ull;

#pragma unroll 2
    for (int k = 0; k < 128; k += 2) {
        float4 wa = *(const float4*)&Ws[k * 128 + 4 * ct];
        float4 wb = *(const float4*)&Ws[(k + 1) * 128 + 4 * ct];
        u64 w0 = pk2(wa.x, wb.x), w1 = pk2(wa.y, wb.y);
        u64 w2 = pk2(wa.z, wb.z), w3 = pk2(wa.w, wb.w);
#pragma unroll
        for (int i = 0; i < 8; i++) {
            u64 xp = *(const u64*)&xs[(rt * 8 + i) * 132 + k];
            ffma2(acc2[i][0], xp, w0);
            ffma2(acc2[i][1], xp, w1);
            ffma2(acc2[i][2], xp, w2);
            ffma2(acc2[i][3], xp, w3);
        }
    }

    float4 avs = *(const float4*)&atts[4 * ct];
    float4 avd = *(const float4*)&attd[4 * ct];
#pragma unroll
    for (int i = 0; i < 8; i++) {
        float a[4];
#pragma unroll
        for (int c = 0; c < 4; c++) {
            float lo, hi; upk2(lo, hi, acc2[i][c]);
            a[c] = lo + hi;
        }
        int row = row0 + rt * 8 + i;   // uniform across warp
        if (row < NN) {
            *(float4*)&g_h1[row * 128 + 4 * ct] = make_float4(a[0], a[1], a[2], a[3]);
            float ps = a[0] * avs.x + a[1] * avs.y + a[2] * avs.z + a[3] * avs.w;
            float pd = a[0] * avd.x + a[1] * avd.y + a[2] * avd.z + a[3] * avd.w;
            ps += __shfl_xor_sync(0xffffffffu, ps, 1);
            ps += __shfl_xor_sync(0xffffffffu, ps, 2);
            pd += __shfl_xor_sync(0xffffffffu, pd, 1);
            pd += __shfl_xor_sync(0xffffffffu, pd, 2);
            if ((ct & 3) == 0) {
                g_as1[row * 8 + (ct >> 2)] = ps;
                g_ad1[row * 8 + (ct >> 2)] = pd;
            }
        }
    }
}

// ==================== fused layer1: denom + aggregate + bias + ELU ====================
__global__ void l1_gather(const float* __restrict__ b1) {
    int w = (blockIdx.x * blockDim.x + threadIdx.x) >> 5;
    int lane = threadIdx.x & 31;
    if (w >= NN) return;
    int beg = g_rp[w], end = g_rp[w + 1];

    float ad[8];
#pragma unroll
    for (int h = 0; h < 8; h++) ad[h] = g_ad1[w * 8 + h];

    float dn[8] = {};
    for (int e = beg + lane; e < end; e += 32) {
        int s = g_col[e];
        float4 s0 = *(const float4*)&g_as1[s * 8];
        float4 s1 = *(const float4*)&g_as1[s * 8 + 4];
        dn[0] += __expf(lrelu(s0.x + ad[0]));
        dn[1] += __expf(lrelu(s0.y + ad[1]));
        dn[2] += __expf(lrelu(s0.z + ad[2]));
        dn[3] += __expf(lrelu(s0.w + ad[3]));
        dn[4] += __expf(lrelu(s1.x + ad[4]));
        dn[5] += __expf(lrelu(s1.y + ad[5]));
        dn[6] += __expf(lrelu(s1.z + ad[6]));
        dn[7] += __expf(lrelu(s1.w + ad[7]));
    }
#pragma unroll
    for (int h = 0; h < 8; h++)
        for (int off = 16; off; off >>= 1)
            dn[h] += __shfl_xor_sync(0xffffffffu, dn[h], off);

    int h = lane >> 2;
    float adh = ad[h];
    float rdn = 1.f / (dn[h] + 1e-16f);

    float4 acc = make_float4(0.f, 0.f, 0.f, 0.f);
    for (int base = beg; base < end; base += 32) {
        int idx = base + lane;
        int sc = (idx < end) ? g_col[idx] : 0;
        int n = min(32, end - base);
#pragma unroll 8
        for (int j = 0; j < n; j++) {
            int s = __shfl_sync(0xffffffffu, sc, j);
            float a = __expf(lrelu(g_as1[s * 8 + h] + adh)) * rdn;
            float4 v = *(const float4*)&g_h1[s * 128 + lane * 4];
            acc.x += a * v.x; acc.y += a * v.y;
            acc.z += a * v.z; acc.w += a * v.w;
        }
    }

    float4 bb = *(const float4*)&b1[lane * 4];
    acc.x += bb.x; acc.y += bb.y; acc.z += bb.z; acc.w += bb.w;
    acc.x = acc.x > 0.f ? acc.x : expm1f(acc.x);
    acc.y = acc.y > 0.f ? acc.y : expm1f(acc.y);
    acc.z = acc.z > 0.f ? acc.z : expm1f(acc.z);
    acc.w = acc.w > 0.f ? acc.w : expm1f(acc.w);
    *(float4*)&g_o1[w * 128 + lane * 4] = acc;
}

// ==================== GEMM2 (128->40, f32x2) with fused a2 attention dots ====================
__global__ void gemm2_kernel(const float* __restrict__ W,
                             const float* __restrict__ atts, const float* __restrict__ attd) {
    extern __shared__ float sm[];
    float* Ws = sm;                  // 128*40 = 5120
    float* xs = sm + 5120;           // 64*132 = 8448
    float* sa = sm + 5120 + 8448;    // 64
    float* sd = sa + 64;             // 64
    int t = threadIdx.x;
    int ct = t % 10, rt = t / 10;
    int row0 = blockIdx.x * 64;

    for (int i = t; i < 5120; i += 160) Ws[i] = W[i];
    for (int i = t; i < 2048; i += 160) {
        int r = i >> 5, k4 = (i & 31) * 4;
        int row = row0 + r;
        float4 v = (row < NN) ? *(const float4*)&g_o1[row * 128 + k4]
                              : make_float4(0.f, 0.f, 0.f, 0.f);
        *(float4*)&xs[r * 132 + k4] = v;
    }
    if (t < 64) { sa[t] = 0.f; sd[t] = 0.f; }
    __syncthreads();

    u64 acc2[4][4];
#pragma unroll
    for (int i = 0; i < 4; i++)
#pragma unroll
        for (int c = 0; c < 4; c++) acc2[i][c] = 0ull;

#pragma unroll 2
    for (int k = 0; k < 128; k += 2) {
        float4 wa = *(const float4*)&Ws[k * 40 + 4 * ct];
        float4 wb = *(const float4*)&Ws[(k + 1) * 40 + 4 * ct];
        u64 w0 = pk2(wa.x, wb.x), w1 = pk2(wa.y, wb.y);
        u64 w2 = pk2(wa.z, wb.z), w3 = pk2(wa.w, wb.w);
#pragma unroll
        for (int i = 0; i < 4; i++) {
            u64 xp = *(const u64*)&xs[(rt * 4 + i) * 132 + k];
            ffma2(acc2[i][0], xp, w0);
            ffma2(acc2[i][1], xp, w1);
            ffma2(acc2[i][2], xp, w2);
            ffma2(acc2[i][3], xp, w3);
        }
    }

    float4 avs = *(const float4*)&atts[4 * ct];
    float4 avd = *(const float4*)&attd[4 * ct];
#pragma unroll
    for (int i = 0; i < 4; i++) {
        float a[4];
#pragma unroll
        for (int c = 0; c < 4; c++) {
            float lo, hi; upk2(lo, hi, acc2[i][c]);
            a[c] = lo + hi;
        }
        int row = row0 + rt * 4 + i;
        if (row < NN)
            *(float4*)&g_z[row * 40 + 4 * ct] = make_float4(a[0], a[1], a[2], a[3]);
        float ps = a[0] * avs.x + a[1] * avs.y + a[2] * avs.z + a[3] * avs.w;
        float pd = a[0] * avd.x + a[1] * avd.y + a[2] * avd.z + a[3] * avd.w;
        atomicAdd(&sa[rt * 4 + i], ps);
        atomicAdd(&sd[rt * 4 + i], pd);
    }
    __syncthreads();
    if (t < 64) {
        int row = row0 + t;
        if (row < NN) { g_as2[row] = sa[t]; g_ad2[row] = sd[t]; }
    }
}

// ==================== fused layer2: denom + aggregate + bias + log_softmax ====================
__global__ void l2_gather(float* __restrict__ out, const float* __restrict__ b2) {
    int w = (blockIdx.x * blockDim.x + threadIdx.x) >> 5;
    int lane = threadIdx.x & 31;
    if (w >= NN) return;
    int beg = g_rp[w], end = g_rp[w + 1];
    float adw = g_ad2[w];

    float dn = 0.f;
    for (int e = beg + lane; e < end; e += 32)
        dn += __expf(lrelu(g_as2[g_col[e]] + adw));
    for (int off = 16; off; off >>= 1)
        dn += __shfl_xor_sync(0xffffffffu, dn, off);
    float rdn = 1.f / (dn + 1e-16f);

    float a1 = 0.f, a2 = 0.f;
    for (int base = beg; base < end; base += 32) {
        int idx = base + lane;
        int sc = (idx < end) ? g_col[idx] : 0;
        int n = min(32, end - base);
#pragma unroll 8
        for (int j = 0; j < n; j++) {
            int s = __shfl_sync(0xffffffffu, sc, j);
            float al = __expf(lrelu(g_as2[s] + adw)) * rdn;
            a1 += al * g_z[s * 40 + lane];
            if (lane < 8) a2 += al * g_z[s * 40 + 32 + lane];
        }
    }

    float v1 = a1 + b2[lane];
    float v2 = (lane < 8) ? a2 + b2[32 + lane] : -1e30f;
    float m = fmaxf(v1, v2);
    for (int o = 16; o; o >>= 1) m = fmaxf(m, __shfl_xor_sync(0xffffffffu, m, o));
    float s = expf(v1 - m) + ((lane < 8) ? expf(v2 - m) : 0.f);
    for (int o = 16; o; o >>= 1) s += __shfl_xor_sync(0xffffffffu, s, o);
    float ls = m + logf(s);
    out[w * 40 + lane] = v1 - ls;
    if (lane < 8) out[w * 40 + 32 + lane] = v2 - ls;
}

// ==================== launch ====================
extern "C" void kernel_launch(void* const* d_in, const int* in_sizes, int n_in,
                              void* d_out, int out_size) {
    const float* x   = (const float*)d_in[0];
    const int*   ei  = (const int*)d_in[1];
    const float* W1  = (const float*)d_in[2];
    const float* as1 = (const float*)d_in[3];
    const float* ad1 = (const float*)d_in[4];
    const float* b1  = (const float*)d_in[5];
    const float* W2  = (const float*)d_in[6];
    const float* as2 = (const float*)d_in[7];
    const float* ad2 = (const float*)d_in[8];
    const float* b2  = (const float*)d_in[9];
    float* out = (float*)d_out;

    static cudaStream_t sB = nullptr;
    static cudaEvent_t evF = nullptr, evJ = nullptr;
    if (!sB) {
        cudaStreamCreateWithFlags(&sB, cudaStreamNonBlocking);
        cudaEventCreateWithFlags(&evF, cudaEventDisableTiming);
        cudaEventCreateWithFlags(&evJ, cudaEventDisableTiming);
    }

    const int SM1 = (16384 + 64 * 132) * 4;          // 99328 B
    const int SM2 = (5120 + 64 * 132 + 128) * 4;     // 54784 B
    cudaFuncSetAttribute(gemm1_kernel, cudaFuncAttributeMaxDynamicSharedMemorySize, SM1);
    cudaFuncSetAttribute(gemm2_kernel, cudaFuncAttributeMaxDynamicSharedMemorySize, SM2);

    // fork: CSR build on side stream, gemm1 on main stream
    cudaEventRecord(evF, 0);
    cudaStreamWaitEvent(sB, evF, 0);

    hist_kernel<<<(ET + 255) / 256, 256, 0, sB>>>(ei);   // g_deg zeroed by prior scatter / bss
    scan1<<<NB, 1024, 0, sB>>>();
    scan2<<<1, 128, 0, sB>>>();
    scan3<<<(NN + 255) / 256, 256, 0, sB>>>();
    scatter<<<(ET + 255) / 256, 256, 0, sB>>>(ei);
    cudaEventRecord(evJ, sB);

    gemm1_kernel<<<(NN + 63) / 64, 256, SM1>>>(x, W1, as1, ad1);

    // join
    cudaStreamWaitEvent(0, evJ, 0);

    l1_gather<<<(NN * 32 + 255) / 256, 256>>>(b1);
    gemm2_kernel<<<(NN + 63) / 64, 160, SM2>>>(W2, as2, ad2);
    l2_gather<<<(NN * 32 + 255) / 256, 256>>>(out, b2);
}